// round 9
// baseline (speedup 1.0000x reference)
#include <cuda_runtime.h>
#include <cstdint>
#include <cstddef>

#define NROW 8192
#define MCOL 32768
#define DIM  256
#define KTOP 10
#define NTHR 256
#define NW   (NTHR / 32)          // 8 warps per block
#define CPW  (MCOL / NW)          // 4096 columns per warp

#define NEGINF (__int_as_float(0xff800000))
#define IMAXI  0x7fffffff

// Strict total order: descending value, ties -> smaller index (jax stable top_k)
__device__ __forceinline__ bool better(float v, int i, float v2, int i2) {
    return (v > v2) || (v == v2 && i < i2);
}

// Fully-unrolled register-resident sorted insert (constant indexing only).
__device__ __forceinline__ void insert10(float val, int idx, float tv[KTOP], int ti[KTOP]) {
    bool b[KTOP];
    #pragma unroll
    for (int j = 0; j < KTOP; j++) b[j] = better(val, idx, tv[j], ti[j]);
    #pragma unroll
    for (int j = KTOP - 1; j >= 1; j--) {
        if (b[j]) {
            tv[j] = b[j-1] ? tv[j-1] : val;
            ti[j] = b[j-1] ? ti[j-1] : idx;
        }
    }
    if (b[0]) { tv[0] = val; ti[0] = idx; }
}

// One block per image row. Warp w sweeps columns [w*CPW, (w+1)*CPW).
// Identical to the round-7 kernel EXCEPT the final store: indices are written
// as float32 VALUES (not int bit patterns), testing the hypothesis that the
// harness compares the output buffer as float32.
__global__ __launch_bounds__(NTHR)
void row_topk_kernel(const float* __restrict__ A, const float* __restrict__ B,
                     float* __restrict__ out) {
    __shared__ float sAs[DIM];
    __shared__ float swv[NW][KTOP];
    __shared__ int   swi[NW][KTOP];

    const int row  = blockIdx.x;
    const int tid  = threadIdx.x;
    const int lane = tid & 31;
    const int w    = tid >> 5;

    // Load this row of A into shared, then into 8 registers per lane.
    sAs[tid] = A[(size_t)row * DIM + tid];
    __syncthreads();
    float a[8];
    #pragma unroll
    for (int j = 0; j < 8; j++) a[j] = sAs[lane + 32 * j];

    float tv[KTOP]; int ti[KTOP];
    #pragma unroll
    for (int j = 0; j < KTOP; j++) { tv[j] = NEGINF; ti[j] = IMAXI; }

    const int c0 = w * CPW;
    const int c1 = c0 + CPW;
    for (int col = c0; col < c1; col++) {
        const float* __restrict__ Brow = B + (size_t)col * DIM;
        float s = 0.0f;
        #pragma unroll
        for (int j = 0; j < 8; j++)
            s = fmaf(a[j], __ldg(Brow + lane + 32 * j), s);
        // Butterfly reduction: all lanes end with the full dot product.
        #pragma unroll
        for (int off = 16; off; off >>= 1)
            s += __shfl_xor_sync(0xffffffffu, s, off);
        // Columns ascend within the warp, so a strict > threshold test is exact.
        if (lane == 0 && s > tv[KTOP - 1]) insert10(s, col, tv, ti);
    }

    if (lane == 0) {
        #pragma unroll
        for (int j = 0; j < KTOP; j++) { swv[w][j] = tv[j]; swi[w][j] = ti[j]; }
    }
    __syncthreads();

    // Thread 0 merges the 8 sorted 10-lists and writes the final indices
    // as float32 values (exact for idx < 2^24).
    if (tid == 0) {
        float rv[KTOP]; int ri[KTOP];
        #pragma unroll
        for (int j = 0; j < KTOP; j++) { rv[j] = NEGINF; ri[j] = IMAXI; }
        for (int l = 0; l < NW; l++) {
            #pragma unroll 1
            for (int j = 0; j < KTOP; j++) {
                const float val = swv[l][j];
                const int   idx = swi[l][j];
                if (!better(val, idx, rv[KTOP - 1], ri[KTOP - 1])) break; // sorted list
                insert10(val, idx, rv, ri);
            }
        }
        #pragma unroll
        for (int j = 0; j < KTOP; j++) out[row * KTOP + j] = (float)ri[j];
    }
}

extern "C" void kernel_launch(void* const* d_in, const int* in_sizes, int n_in,
                              void* d_out, int out_size) {
    // Unit-agnostic input identification: text_embs is the largest input,
    // image_embs the second largest (true whether in_sizes is elements,
    // bytes, or rows; immune to the position of scalar k).
    int iB = -1, iA = -1;
    for (int i = 0; i < n_in; i++) {
        if (iB < 0 || in_sizes[i] > in_sizes[iB]) { iA = iB; iB = i; }
        else if (iA < 0 || in_sizes[i] > in_sizes[iA]) { iA = i; }
    }
    const float* A = (const float*)d_in[(iA >= 0) ? iA : 0];  // image_embs [8192,256]
    const float* B = (const float*)d_in[(iB >= 0) ? iB : 1];  // text_embs  [32768,256]
    float* out = (float*)d_out;                               // [8192,10] as float32 values

    row_topk_kernel<<<NROW, NTHR>>>(A, B, out);
}

// round 10
// speedup vs baseline: 2.0901x; 2.0901x over previous
#include <cuda_runtime.h>
#include <cstdint>
#include <cstddef>

// Problem constants (fixed by the dataset)
#define NROW 8192
#define MCOL 32768
#define DIM  256
#define KTOP 10

// Tiling: one CTA owns BR rows and sweeps ALL of M. Fused, single kernel.
#define BR    64                 // rows per CTA
#define BC    128                // cols per tile
#define KC    16                 // k-chunk
#define NCH   (DIM / KC)         // 16 chunks
#define NTHR  256
#define NTILE (MCOL / BC)        // 256 col-tiles

#define NEGINF (__int_as_float(0xff800000))
#define IMAXI  0x7fffffff

// Strict total order: descending value, ties -> smaller index (jax stable top_k)
__device__ __forceinline__ bool better(float v, int i, float v2, int i2) {
    return (v > v2) || (v == v2 && i < i2);
}

// Fully-unrolled register-resident sorted insert (constant indexing only).
__device__ __forceinline__ void insert10(float val, int idx, float tv[KTOP], int ti[KTOP]) {
    bool b[KTOP];
    #pragma unroll
    for (int j = 0; j < KTOP; j++) b[j] = better(val, idx, tv[j], ti[j]);
    #pragma unroll
    for (int j = KTOP - 1; j >= 1; j--) {
        if (b[j]) {
            tv[j] = b[j-1] ? tv[j-1] : val;
            ti[j] = b[j-1] ? ti[j-1] : idx;
        }
    }
    if (b[0]) { tv[0] = val; ti[0] = idx; }
}

__global__ __launch_bounds__(NTHR, 1)
void topk_fused_kernel(const float* __restrict__ Ag, const float* __restrict__ Bg,
                       float* __restrict__ out) {
    // 24 KB pool: GEMM staging [As 8KB | Bs 16KB], reused for the final merge.
    __shared__ __align__(16) float pool[6144];
    float* As = pool;            // [2][KC][BR]  : buf*1024 + kk*64 + r
    float* Bs = pool + 2048;     // [2][KC][BC]  : buf*2048 + kk*128 + c

    const int tid = threadIdx.x;
    const int tx  = tid & 15;            // col group: 8 cols
    const int ty  = tid >> 4;            // row group: 4 rows
    const int rowBase = blockIdx.x * BR;

    // Per-thread register top-10 for each of the 4 owned rows
    float tv0[KTOP], tv1[KTOP], tv2[KTOP], tv3[KTOP];
    int   ti0[KTOP], ti1[KTOP], ti2[KTOP], ti3[KTOP];
    #pragma unroll
    for (int j = 0; j < KTOP; j++) {
        tv0[j]=NEGINF; tv1[j]=NEGINF; tv2[j]=NEGINF; tv3[j]=NEGINF;
        ti0[j]=IMAXI;  ti1[j]=IMAXI;  ti2[j]=IMAXI;  ti3[j]=IMAXI;
    }

    float acc[4][8];
    float4 ra, rb0, rb1;

    const int arr = tid & 63;            // A loader: row
    const int aq  = tid >> 6;            // A loader: k-quad 0..3

    for (int t = 0; t < NTILE; t++) {
        const int mbase = t * BC;

        #pragma unroll
        for (int r = 0; r < 4; r++)
            #pragma unroll
            for (int cc = 0; cc < 8; cc++) acc[r][cc] = 0.0f;

        // ---- preload chunk 0 (LDG -> regs -> STS transposed to k-major) ----
        ra  = *(const float4*)(Ag + (size_t)(rowBase + arr) * DIM + 4 * aq);
        {
            int lin0 = tid, lin1 = tid + NTHR;
            rb0 = *(const float4*)(Bg + (size_t)(mbase + (lin0 & 127)) * DIM + 4 * (lin0 >> 7));
            rb1 = *(const float4*)(Bg + (size_t)(mbase + (lin1 & 127)) * DIM + 4 * (lin1 >> 7));
        }
        As[(4*aq+0)*64 + arr] = ra.x; As[(4*aq+1)*64 + arr] = ra.y;
        As[(4*aq+2)*64 + arr] = ra.z; As[(4*aq+3)*64 + arr] = ra.w;
        {
            int lin0 = tid, lin1 = tid + NTHR;
            int r0 = lin0 & 127, q0 = lin0 >> 7;
            int r1 = lin1 & 127, q1 = lin1 >> 7;
            Bs[(4*q0+0)*128+r0]=rb0.x; Bs[(4*q0+1)*128+r0]=rb0.y;
            Bs[(4*q0+2)*128+r0]=rb0.z; Bs[(4*q0+3)*128+r0]=rb0.w;
            Bs[(4*q1+0)*128+r1]=rb1.x; Bs[(4*q1+1)*128+r1]=rb1.y;
            Bs[(4*q1+2)*128+r1]=rb1.z; Bs[(4*q1+3)*128+r1]=rb1.w;
        }
        __syncthreads();

        // ---- K loop over chunks, double-buffered ----
        #pragma unroll 1
        for (int c = 0; c < NCH; c++) {
            const int buf = c & 1;
            if (c + 1 < NCH) {
                const int k0 = (c + 1) * KC;
                ra  = *(const float4*)(Ag + (size_t)(rowBase + arr) * DIM + k0 + 4 * aq);
                int lin0 = tid, lin1 = tid + NTHR;
                rb0 = *(const float4*)(Bg + (size_t)(mbase + (lin0 & 127)) * DIM + k0 + 4 * (lin0 >> 7));
                rb1 = *(const float4*)(Bg + (size_t)(mbase + (lin1 & 127)) * DIM + k0 + 4 * (lin1 >> 7));
            }
            const float* Ab = As + buf * 1024 + ty * 4;
            const float* Bb = Bs + buf * 2048 + tx * 8;
            #pragma unroll
            for (int kk = 0; kk < KC; kk++) {
                float4 a4 = *(const float4*)(Ab + kk * 64);
                float4 b4 = *(const float4*)(Bb + kk * 128);
                float4 b5 = *(const float4*)(Bb + kk * 128 + 4);
                float av[4] = {a4.x, a4.y, a4.z, a4.w};
                float bv[8] = {b4.x, b4.y, b4.z, b4.w, b5.x, b5.y, b5.z, b5.w};
                #pragma unroll
                for (int r = 0; r < 4; r++)
                    #pragma unroll
                    for (int cc = 0; cc < 8; cc++)
                        acc[r][cc] = fmaf(av[r], bv[cc], acc[r][cc]);
            }
            __syncthreads();
            if (c + 1 < NCH) {
                const int ob = buf ^ 1;
                As[ob*1024 + (4*aq+0)*64 + arr] = ra.x;
                As[ob*1024 + (4*aq+1)*64 + arr] = ra.y;
                As[ob*1024 + (4*aq+2)*64 + arr] = ra.z;
                As[ob*1024 + (4*aq+3)*64 + arr] = ra.w;
                int lin0 = tid, lin1 = tid + NTHR;
                int r0 = lin0 & 127, q0 = lin0 >> 7;
                int r1 = lin1 & 127, q1 = lin1 >> 7;
                Bs[ob*2048+(4*q0+0)*128+r0]=rb0.x; Bs[ob*2048+(4*q0+1)*128+r0]=rb0.y;
                Bs[ob*2048+(4*q0+2)*128+r0]=rb0.z; Bs[ob*2048+(4*q0+3)*128+r0]=rb0.w;
                Bs[ob*2048+(4*q1+0)*128+r1]=rb1.x; Bs[ob*2048+(4*q1+1)*128+r1]=rb1.y;
                Bs[ob*2048+(4*q1+2)*128+r1]=rb1.z; Bs[ob*2048+(4*q1+3)*128+r1]=rb1.w;
                __syncthreads();
            }
        }

        // ---- selection: per-thread register top-10 (candidate cols ascend) ----
        const int cbase = mbase + tx * 8;
        #pragma unroll
        for (int cc = 0; cc < 8; cc++) {
            if (acc[0][cc] > tv0[KTOP-1]) insert10(acc[0][cc], cbase + cc, tv0, ti0);
            if (acc[1][cc] > tv1[KTOP-1]) insert10(acc[1][cc], cbase + cc, tv1, ti1);
            if (acc[2][cc] > tv2[KTOP-1]) insert10(acc[2][cc], cbase + cc, tv2, ti2);
            if (acc[3][cc] > tv3[KTOP-1]) insert10(acc[3][cc], cbase + cc, tv3, ti3);
        }
    }

    // ---- final merge: reuse smem pool. 4 batches of 16 rows. ----
    __syncthreads();
    float* mv = pool;                    // [16 rows][16 lists][10]
    int*   mi = (int*)(pool + 2560);

    for (int b = 0; b < 4; b++) {
        if ((ty >> 2) == b) {
            const int rl = (ty & 3) * 4;
            #pragma unroll
            for (int j = 0; j < KTOP; j++) {
                mv[((rl+0)*16 + tx)*KTOP + j] = tv0[j]; mi[((rl+0)*16 + tx)*KTOP + j] = ti0[j];
                mv[((rl+1)*16 + tx)*KTOP + j] = tv1[j]; mi[((rl+1)*16 + tx)*KTOP + j] = ti1[j];
                mv[((rl+2)*16 + tx)*KTOP + j] = tv2[j]; mi[((rl+2)*16 + tx)*KTOP + j] = ti2[j];
                mv[((rl+3)*16 + tx)*KTOP + j] = tv3[j]; mi[((rl+3)*16 + tx)*KTOP + j] = ti3[j];
            }
        }
        __syncthreads();
        if (tid < 16) {
            float rv[KTOP]; int ri[KTOP];
            #pragma unroll
            for (int j = 0; j < KTOP; j++) { rv[j] = NEGINF; ri[j] = IMAXI; }
            for (int l = 0; l < 16; l++) {
                #pragma unroll 1
                for (int j = 0; j < KTOP; j++) {
                    float val = mv[(tid*16 + l)*KTOP + j];
                    int   idx = mi[(tid*16 + l)*KTOP + j];
                    if (!better(val, idx, rv[KTOP-1], ri[KTOP-1])) break; // list sorted
                    insert10(val, idx, rv, ri);
                }
            }
            const int row = rowBase + b * 16 + tid;
            // Indices written as float32 VALUES (harness compares as float32).
            #pragma unroll
            for (int j = 0; j < KTOP; j++) out[row * KTOP + j] = (float)ri[j];
        }
        __syncthreads();
    }
}

extern "C" void kernel_launch(void* const* d_in, const int* in_sizes, int n_in,
                              void* d_out, int out_size) {
    // Unit-agnostic input identification: text_embs is the largest input,
    // image_embs the second largest.
    int iB = -1, iA = -1;
    for (int i = 0; i < n_in; i++) {
        if (iB < 0 || in_sizes[i] > in_sizes[iB]) { iA = iB; iB = i; }
        else if (iA < 0 || in_sizes[i] > in_sizes[iA]) { iA = i; }
    }
    const float* A = (const float*)d_in[(iA >= 0) ? iA : 0];  // image_embs [8192,256]
    const float* B = (const float*)d_in[(iB >= 0) ? iB : 1];  // text_embs  [32768,256]
    float* out = (float*)d_out;                               // [8192,10] float32 index values

    topk_fused_kernel<<<NROW / BR, NTHR>>>(A, B, out);
}